// round 7
// baseline (speedup 1.0000x reference)
#include <cuda_runtime.h>
#include <math_constants.h>

#define BATCH 32
#define NROWS 4096
#define HDIM  256
#define H4    (HDIM / 4)          // 64 float4 per row
#define NGRP  512
#define KIDX  16

// scratch: per-(row, channel) max over batch. 4096*256 fp32 = 4 MB, alloc-free.
__device__ float4 g_bmax[NROWS * H4];

// Kernel 1: bmax[a][h] = max over 32 batches of x[b,a,h].
// One thread per (row, float4-chunk): 4096*64 = 262144 threads.
// Consecutive threads -> consecutive float4 within a row -> fully coalesced.
// Batch stride = 4 MB: 32 streaming reads per thread; unroll gives MLP.
__global__ __launch_bounds__(256) void batchmax_kernel(const float4* __restrict__ x) {
    const int i = blockIdx.x * blockDim.x + threadIdx.x;   // 0 .. NROWS*H4-1
    const float4* p = x + i;

    float4 m = make_float4(-CUDART_INF_F, -CUDART_INF_F, -CUDART_INF_F, -CUDART_INF_F);
    #pragma unroll 8
    for (int b = 0; b < BATCH; ++b) {
        float4 v = p[(size_t)b * (NROWS * H4)];
        m.x = fmaxf(m.x, v.x);
        m.y = fmaxf(m.y, v.y);
        m.z = fmaxf(m.z, v.z);
        m.w = fmaxf(m.w, v.w);
    }
    g_bmax[i] = m;
}

// Kernel 2: out[g][h] = max over the 16 rows idx[g,k] of bmax[row][h].
// One block per group (512 blocks), 64 threads = one float4 chunk each.
// The bmax table (4 MB) is L2-resident; idx row (16 ints) loaded by all lanes.
__global__ __launch_bounds__(64) void groupmax_kernel(const int* __restrict__ idx,
                                                      float4* __restrict__ out) {
    const int g = blockIdx.x;
    const int c = threadIdx.x;                // 0..63 float4 chunk

    const int* gi = idx + g * KIDX;
    float4 m = make_float4(-CUDART_INF_F, -CUDART_INF_F, -CUDART_INF_F, -CUDART_INF_F);
    #pragma unroll
    for (int k = 0; k < KIDX; ++k) {
        const float4 v = g_bmax[gi[k] * H4 + c];
        m.x = fmaxf(m.x, v.x);
        m.y = fmaxf(m.y, v.y);
        m.z = fmaxf(m.z, v.z);
        m.w = fmaxf(m.w, v.w);
    }
    out[g * H4 + c] = m;
}

extern "C" void kernel_launch(void* const* d_in, const int* in_sizes, int n_in,
                              void* d_out, int out_size) {
    const float4* x = (const float4*)d_in[0];   // (32, 4096*256) fp32
    const int*  idx = (const int*)d_in[1];      // (512, 16) int32
    float4*     out = (float4*)d_out;           // 512*256 fp32 = 2048 float4

    batchmax_kernel<<<(NROWS * H4) / 256, 256>>>(x);
    groupmax_kernel<<<NGRP, 64>>>(idx, out);
    (void)in_sizes; (void)n_in; (void)out_size;
}

// round 9
// speedup vs baseline: 1.1537x; 1.1537x over previous
#include <cuda_runtime.h>
#include <math_constants.h>

#define BATCH 32
#define NROWS 4096
#define HDIM  256
#define H4    (HDIM / 4)          // 64 float4 per row
#define NGRP  512
#define KIDX  16
#define NOUT_IDX (NGRP * KIDX)    // 8192

// scratch: per-(row, channel) max over batch. 4 MB, alloc-free.
__device__ float4 g_bmax[NROWS * H4];
// which rows are referenced by idx this call (zeroed by groupmax for the next call)
__device__ unsigned char g_mask[NROWS];

// Kernel 0: flag referenced rows. Races write the same value (1) - benign.
__global__ __launch_bounds__(256) void set_mask_kernel(const int* __restrict__ idx) {
    const int i = blockIdx.x * blockDim.x + threadIdx.x;
    if (i < NOUT_IDX) g_mask[idx[i]] = 1;
}

// Kernel 1: bmax[a][h] = max over 32 batches of x[b,a,h], only for flagged rows.
// One thread per (row, float4-chunk). Consecutive threads -> consecutive float4
// within a row -> fully coalesced streaming reads (batch stride 4 MB).
__global__ __launch_bounds__(256) void batchmax_kernel(const float4* __restrict__ x) {
    const int i   = blockIdx.x * blockDim.x + threadIdx.x;   // 0 .. NROWS*H4-1
    const int row = i >> 6;
    if (!g_mask[row]) return;        // ~13.5% of rows are never gathered

    const float4* p = x + i;
    float4 m = make_float4(-CUDART_INF_F, -CUDART_INF_F, -CUDART_INF_F, -CUDART_INF_F);
    #pragma unroll 8
    for (int b = 0; b < BATCH; ++b) {
        float4 v = p[(size_t)b * (NROWS * H4)];
        m.x = fmaxf(m.x, v.x);
        m.y = fmaxf(m.y, v.y);
        m.z = fmaxf(m.z, v.z);
        m.w = fmaxf(m.w, v.w);
    }
    g_bmax[i] = m;
}

// Kernel 2: out[g][h] = max over the 16 rows idx[g,k] of bmax[row][h].
// 256 threads per group: 4 K-subsets x 64 chunks, smem tree-reduce.
// Also resets g_mask for the next graph replay (batchmax is already done,
// so kernel-boundary ordering makes this safe and deterministic).
__global__ __launch_bounds__(256) void groupmax_kernel(const int* __restrict__ idx,
                                                       float4* __restrict__ out) {
    const int g   = blockIdx.x;
    const int tid = threadIdx.x;

    // reset mask for next call (first 16 blocks cover all 4096 rows)
    const int gt = g * 256 + tid;
    if (gt < NROWS) g_mask[gt] = 0;

    __shared__ int sidx[KIDX];
    if (tid < KIDX) sidx[tid] = idx[g * KIDX + tid];
    __syncthreads();

    const int k4 = tid >> 6;         // 0..3 : which 4 indices
    const int c  = tid & 63;         // 0..63: float4 chunk

    float4 m = make_float4(-CUDART_INF_F, -CUDART_INF_F, -CUDART_INF_F, -CUDART_INF_F);
    #pragma unroll
    for (int k = k4 * 4; k < k4 * 4 + 4; ++k) {
        const float4 v = g_bmax[sidx[k] * H4 + c];
        m.x = fmaxf(m.x, v.x);
        m.y = fmaxf(m.y, v.y);
        m.z = fmaxf(m.z, v.z);
        m.w = fmaxf(m.w, v.w);
    }

    __shared__ float4 s[256];
    s[tid] = m;
    __syncthreads();

    if (k4 == 0) {
        #pragma unroll
        for (int j = 1; j < 4; ++j) {
            const float4 v = s[j * 64 + c];
            m.x = fmaxf(m.x, v.x);
            m.y = fmaxf(m.y, v.y);
            m.z = fmaxf(m.z, v.z);
            m.w = fmaxf(m.w, v.w);
        }
        out[g * H4 + c] = m;
    }
}

extern "C" void kernel_launch(void* const* d_in, const int* in_sizes, int n_in,
                              void* d_out, int out_size) {
    const float4* x = (const float4*)d_in[0];   // (32, 4096*256) fp32
    const int*  idx = (const int*)d_in[1];      // (512, 16) int32
    float4*     out = (float4*)d_out;           // 512*256 fp32 = 2048 float4

    set_mask_kernel<<<NOUT_IDX / 256, 256>>>(idx);
    batchmax_kernel<<<(NROWS * H4) / 256, 256>>>(x);
    groupmax_kernel<<<NGRP, 256>>>(idx, out);
    (void)in_sizes; (void)n_in; (void)out_size;
}